// round 1
// baseline (speedup 1.0000x reference)
#include <cuda_runtime.h>

// SIR RK4 integrator: B=65536 systems, params[b] = (beta, gamma, S0, I0)
// out[b][t][c], t in [0,200), c in {S,I,R}; 199 steps of dt=100/199, 8 RK4 substeps each.
//
// Strategy: 2 systems per thread, packed into f32x2 (64-bit) registers, all math
// via mul.rn.f32x2 / fma.rn.f32x2 (Blackwell packed fp32 — 2x fma-pipe throughput,
// ptxas will not emit FFMA2 from plain C++).
//
// Reformulation: deriv k = (-p, p - q, q) with p = beta*S*I, q = gamma*I.
// Only (S, I) feed the stages; accumulate accP = p1+2p2+2p3+p4, accQ likewise,
// final update S -= (h/6)accP; I += (h/6)(accP - accQ); R += (h/6)accQ.

#define NUM_T    200
#define STEPS    199
#define SUBSTEPS 8

typedef unsigned long long u64;

__device__ __forceinline__ u64 pk2(float lo, float hi) {
    u64 r;
    asm("mov.b64 %0, {%1, %2};" : "=l"(r) : "f"(lo), "f"(hi));
    return r;
}
__device__ __forceinline__ void upk2(u64 x, float& lo, float& hi) {
    asm("mov.b64 {%0, %1}, %2;" : "=f"(lo), "=f"(hi) : "l"(x));
}
__device__ __forceinline__ u64 mul2(u64 a, u64 b) {
    u64 r;
    asm("mul.rn.f32x2 %0, %1, %2;" : "=l"(r) : "l"(a), "l"(b));
    return r;
}
__device__ __forceinline__ u64 fma2(u64 a, u64 b, u64 c) {
    u64 r;
    asm("fma.rn.f32x2 %0, %1, %2, %3;" : "=l"(r) : "l"(a), "l"(b), "l"(c));
    return r;
}

__global__ __launch_bounds__(256)
void sir_rk4_kernel(const float* __restrict__ params,
                    float* __restrict__ out,
                    int B)
{
    const int tid = blockIdx.x * blockDim.x + threadIdx.x;
    const int bA = tid * 2;
    if (bA >= B) return;
    const int bB = bA + 1;              // B = 65536 is even; bB always valid
    const bool hasB = (bB < B);

    // ---- load params (coalesced float4 per system) ----
    const float4 pA = reinterpret_cast<const float4*>(params)[bA];
    const float4 pB = hasB ? reinterpret_cast<const float4*>(params)[bB] : pA;

    const u64 beta  = pk2(pA.x, pB.x);
    const u64 gamma = pk2(pA.y, pB.y);

    const float RA0 = 1.0f - pA.z - pA.w;
    const float RB0 = 1.0f - pB.z - pB.w;

    u64 S = pk2(pA.z, pB.z);
    u64 I = pk2(pA.w, pB.w);
    u64 R = pk2(RA0, RB0);

    // ---- step constants (uniform) ----
    const float DT  = 100.0f / 199.0f;
    const float H   = DT / (float)SUBSTEPS;
    const float H2f = 0.5f * H;
    const float C6f = H / 6.0f;

    const u64 h   = pk2(H,    H);
    const u64 nh  = pk2(-H,  -H);
    const u64 h2  = pk2(H2f,  H2f);
    const u64 nh2 = pk2(-H2f, -H2f);
    const u64 c6  = pk2(C6f,  C6f);
    const u64 nc6 = pk2(-C6f, -C6f);
    const u64 two = pk2(2.0f, 2.0f);
    const u64 one = pk2(1.0f, 1.0f);

    // ---- output rows ----
    float* rowA = out + (size_t)bA * (NUM_T * 3);
    float* rowB = out + (size_t)bB * (NUM_T * 3);

    // t = 0
    rowA[0] = pA.z; rowA[1] = pA.w; rowA[2] = RA0;
    if (hasB) { rowB[0] = pB.z; rowB[1] = pB.w; rowB[2] = RB0; }

    for (int t = 1; t < NUM_T; ++t) {
#pragma unroll
        for (int s = 0; s < SUBSTEPS; ++s) {
            // stage 1
            u64 u  = mul2(S, I);
            u64 p1 = mul2(beta, u);
            u64 q1 = mul2(gamma, I);
            u64 S2 = fma2(nh2, p1, S);
            u64 I2 = fma2(h2,  p1, I);
            I2     = fma2(nh2, q1, I2);
            // stage 2
            u      = mul2(S2, I2);
            u64 p2 = mul2(beta, u);
            u64 q2 = mul2(gamma, I2);
            u64 accP = fma2(two, p2, p1);
            u64 accQ = fma2(two, q2, q1);
            u64 S3 = fma2(nh2, p2, S);
            u64 I3 = fma2(h2,  p2, I);
            I3     = fma2(nh2, q2, I3);
            // stage 3
            u      = mul2(S3, I3);
            u64 p3 = mul2(beta, u);
            u64 q3 = mul2(gamma, I3);
            accP   = fma2(two, p3, accP);
            accQ   = fma2(two, q3, accQ);
            u64 S4 = fma2(nh, p3, S);
            u64 I4 = fma2(h,  p3, I);
            I4     = fma2(nh, q3, I4);
            // stage 4
            u      = mul2(S4, I4);
            u64 p4 = mul2(beta, u);
            u64 q4 = mul2(gamma, I4);
            accP   = fma2(one, p4, accP);
            accQ   = fma2(one, q4, accQ);
            // combine
            S = fma2(nc6, accP, S);
            I = fma2(c6,  accP, I);
            I = fma2(nc6, accQ, I);
            R = fma2(c6,  accQ, R);
        }

        float sA, sB, iA, iB, rA, rB;
        upk2(S, sA, sB);
        upk2(I, iA, iB);
        upk2(R, rA, rB);

        float* oA = rowA + t * 3;
        oA[0] = sA; oA[1] = iA; oA[2] = rA;
        if (hasB) {
            float* oB = rowB + t * 3;
            oB[0] = sB; oB[1] = iB; oB[2] = rB;
        }
    }
}

extern "C" void kernel_launch(void* const* d_in, const int* in_sizes, int n_in,
                              void* d_out, int out_size)
{
    const float* params = (const float*)d_in[0];
    float* out = (float*)d_out;
    const int B = in_sizes[0] / 4;          // 65536

    const int nthreads = (B + 1) / 2;       // 2 systems per thread
    const int block = 256;
    const int grid = (nthreads + block - 1) / block;
    sir_rk4_kernel<<<grid, block>>>(params, out, B);
}

// round 3
// speedup vs baseline: 1.0862x; 1.0862x over previous
#include <cuda_runtime.h>

// SIR RK4 integrator: B=65536 systems, params[b] = (beta, gamma, S0, I0)
// out[b][t][c], t in [0,200), c in {S,I,R}; 199 steps of dt=100/199, 8 RK4 substeps each.
//
// R2 (resubmitted after infra failure): reformulated substep with beta/gamma folded
// into per-system step coefficients:
//   u  = S*I
//   S' = fma(-c*beta, u, S)
//   I' = fma( c*beta, u, fma(-c*gamma, I_stage, I_base))
// Critical path per substep: 10 RAW deps (was 17); 23 packed fp32x2 ops (was 31).
// Accumulate raw u-sum and stage-I-sum; final combine applies (h/6)*beta, (h/6)*gamma.

#define NUM_T    200
#define SUBSTEPS 8

typedef unsigned long long u64;

__device__ __forceinline__ u64 pk2(float lo, float hi) {
    u64 r;
    asm("mov.b64 %0, {%1, %2};" : "=l"(r) : "f"(lo), "f"(hi));
    return r;
}
__device__ __forceinline__ void upk2(u64 x, float& lo, float& hi) {
    asm("mov.b64 {%0, %1}, %2;" : "=f"(lo), "=f"(hi) : "l"(x));
}
__device__ __forceinline__ u64 mul2(u64 a, u64 b) {
    u64 r;
    asm("mul.rn.f32x2 %0, %1, %2;" : "=l"(r) : "l"(a), "l"(b));
    return r;
}
__device__ __forceinline__ u64 fma2(u64 a, u64 b, u64 c) {
    u64 r;
    asm("fma.rn.f32x2 %0, %1, %2, %3;" : "=l"(r) : "l"(a), "l"(b), "l"(c));
    return r;
}

__global__ __launch_bounds__(256)
void sir_rk4_kernel(const float* __restrict__ params,
                    float* __restrict__ out,
                    int B)
{
    const int tid = blockIdx.x * blockDim.x + threadIdx.x;
    const int bA = tid * 2;
    if (bA >= B) return;
    const int bB = bA + 1;
    const bool hasB = (bB < B);

    // ---- load params (coalesced float4 per system) ----
    const float4 pA = reinterpret_cast<const float4*>(params)[bA];
    const float4 pB = hasB ? reinterpret_cast<const float4*>(params)[bB] : pA;

    const u64 beta  = pk2(pA.x, pB.x);
    const u64 gamma = pk2(pA.y, pB.y);

    const float RA0 = 1.0f - pA.z - pA.w;
    const float RB0 = 1.0f - pB.z - pB.w;

    u64 S = pk2(pA.z, pB.z);
    u64 I = pk2(pA.w, pB.w);
    u64 R = pk2(RA0, RB0);

    // ---- per-system step coefficients (beta/gamma folded in) ----
    const float DT  = 100.0f / 199.0f;
    const float H   = DT / (float)SUBSTEPS;
    const float H2f = 0.5f * H;
    const float C6f = H / 6.0f;

    const u64 h2v  = pk2(H2f, H2f);
    const u64 hv   = pk2(H,   H);
    const u64 c6v  = pk2(C6f, C6f);
    const u64 two  = pk2(2.0f, 2.0f);
    const u64 one  = pk2(1.0f, 1.0f);
    const u64 m2   = pk2(-2.0f, -2.0f);

    const u64 h2b  = mul2(h2v, beta);                 //  (h/2)*beta
    const u64 nh2b = fma2(h2b, m2, h2b);              // -(h/2)*beta
    const u64 h2g  = mul2(h2v, gamma);
    const u64 nh2g = fma2(h2g, m2, h2g);
    const u64 hb   = mul2(hv, beta);
    const u64 nhb  = fma2(hb, m2, hb);
    const u64 hg   = mul2(hv, gamma);
    const u64 nhg  = fma2(hg, m2, hg);
    const u64 c6b  = mul2(c6v, beta);
    const u64 nc6b = fma2(c6b, m2, c6b);
    const u64 c6g  = mul2(c6v, gamma);
    const u64 nc6g = fma2(c6g, m2, c6g);

    // ---- output rows ----
    float* rowA = out + (size_t)bA * (NUM_T * 3);
    float* rowB = out + (size_t)bB * (NUM_T * 3);

    rowA[0] = pA.z; rowA[1] = pA.w; rowA[2] = RA0;
    if (hasB) { rowB[0] = pB.z; rowB[1] = pB.w; rowB[2] = RB0; }

    for (int t = 1; t < NUM_T; ++t) {
#pragma unroll
        for (int s = 0; s < SUBSTEPS; ++s) {
            // stage 1: k1 at (S, I)
            u64 u1  = mul2(S, I);                   // d1
            u64 in1 = fma2(nh2g, I, I);             // parallel (dep I only)
            u64 S2  = fma2(nh2b, u1, S);            // d2
            u64 I2  = fma2(h2b,  u1, in1);          // d2

            // stage 2: k2 at (S2, I2)
            u64 u2  = mul2(S2, I2);                 // d3
            u64 in2 = fma2(nh2g, I2, I);            // d3
            u64 S3  = fma2(nh2b, u2, S);            // d4
            u64 I3  = fma2(h2b,  u2, in2);          // d4

            // stage 3: k3 at (S3, I3), full step h
            u64 u3  = mul2(S3, I3);                 // d5
            u64 in3 = fma2(nhg, I3, I);             // d5
            u64 S4  = fma2(nhb, u3, S);             // d6
            u64 I4  = fma2(hb,  u3, in3);           // d6

            // stage 4
            u64 u4  = mul2(S4, I4);                 // d7

            // accumulators (off critical path until the end)
            u64 accU = fma2(two, u2, u1);
            accU     = fma2(two, u3, accU);
            accU     = fma2(one, u4, accU);         // d8
            u64 accI = fma2(two, I2, I);
            accI     = fma2(two, I3, accI);
            accI     = fma2(one, I4, accI);

            // combine: S -= (h/6)b*accU; I += (h/6)b*accU - (h/6)g*accI; R += (h/6)g*accI
            S        = fma2(nc6b, accU, S);         // d9
            u64 tI   = fma2(c6b,  accU, I);         // d9
            I        = fma2(nc6g, accI, tI);        // d10
            R        = fma2(c6g,  accI, R);
        }

        float sA, sB, iA, iB, rA, rB;
        upk2(S, sA, sB);
        upk2(I, iA, iB);
        upk2(R, rA, rB);

        float* oA = rowA + t * 3;
        oA[0] = sA; oA[1] = iA; oA[2] = rA;
        if (hasB) {
            float* oB = rowB + t * 3;
            oB[0] = sB; oB[1] = iB; oB[2] = rB;
        }
    }
}

extern "C" void kernel_launch(void* const* d_in, const int* in_sizes, int n_in,
                              void* d_out, int out_size)
{
    const float* params = (const float*)d_in[0];
    float* out = (float*)d_out;
    const int B = in_sizes[0] / 4;          // 65536

    const int nthreads = (B + 1) / 2;       // 2 systems per thread
    const int block = 256;
    const int grid = (nthreads + block - 1) / block;
    sir_rk4_kernel<<<grid, block>>>(params, out, B);
}